// round 1
// baseline (speedup 1.0000x reference)
#include <cuda_runtime.h>
#include <cstdint>

// SimpleZoneODE: the GCN layers in the reference are dead code (their output is
// never consumed by the returned velocity). Effective computation:
//   time_vec = relu(t @ Wt1 + bt1) @ Wt2 + bt2                     [16]
//   c1       = bd1 + person @ Wd1[32:40] + time_vec @ Wd1[40:56]   [64]
//   per row: h1 = relu(ze @ Wd1[0:32] + c1); h2 = relu(h1@Wd2+bd2);
//            out = h2 @ Wd3 + bd3
// Implemented as: tiny prep kernel (computes c1) + fused MLP kernel using
// packed f32x2 FMAs, shared-memory weights, 2 rows per thread.

typedef unsigned long long ull;

__device__ __align__(16) float g_c1[64];

static __device__ __forceinline__ ull fma2(ull a, ull b, ull c) {
    ull d;
    asm("fma.rn.f32x2 %0, %1, %2, %3;" : "=l"(d) : "l"(a), "l"(b), "l"(c));
    return d;
}
static __device__ __forceinline__ ull pack2(float x, float y) {
    ull r;
    asm("mov.b64 %0, {%1, %2};" : "=l"(r) : "f"(x), "f"(y));
    return r;
}
static __device__ __forceinline__ float2 unpack2(ull v) {
    float2 r;
    asm("mov.b64 {%0, %1}, %2;" : "=f"(r.x), "=f"(r.y) : "l"(v));
    return r;
}

// ---------------------------------------------------------------------------
// Prep: compute c1[64] (row-invariant part of the first decoder layer).
// One block of 64 threads; thread j computes c1[j].
// ---------------------------------------------------------------------------
__global__ void prep_kernel(const float* __restrict__ t,
                            const float* __restrict__ person,
                            const float* __restrict__ Wt1,
                            const float* __restrict__ bt1,
                            const float* __restrict__ Wt2,
                            const float* __restrict__ bt2,
                            const float* __restrict__ Wd1,
                            const float* __restrict__ bd1)
{
    const int j = threadIdx.x;  // 0..63
    const float tt = t[0];
    float hid[16];
#pragma unroll
    for (int i = 0; i < 16; i++)
        hid[i] = fmaxf(fmaf(tt, Wt1[i], bt1[i]), 0.f);

    float s = bd1[j];
#pragma unroll
    for (int ii = 0; ii < 16; ii++) {
        float tv = bt2[ii];
#pragma unroll
        for (int i = 0; i < 16; i++)
            tv = fmaf(hid[i], Wt2[i * 16 + ii], tv);
        s = fmaf(tv, Wd1[(40 + ii) * 64 + j], s);
    }
#pragma unroll
    for (int p = 0; p < 8; p++)
        s = fmaf(person[p], Wd1[(32 + p) * 64 + j], s);

    g_c1[j] = s;
}

// ---------------------------------------------------------------------------
// Main fused MLP. 64 threads/block, 2 rows/thread (128 rows/block).
// All weights held in shared memory as 64-bit (float pair) words; all inner
// products use packed fma.rn.f32x2 (2 output columns per instruction).
// ---------------------------------------------------------------------------
__global__ __launch_bounds__(64) void zone_mlp_kernel(
    const float* __restrict__ ze,     // [n,32]
    const float* __restrict__ Wd1,    // [56,64] (only rows 0..31 used here)
    const float* __restrict__ Wd2,    // [64,32]
    const float* __restrict__ bd2,    // [32]
    const float* __restrict__ Wd3,    // [32,32]
    const float* __restrict__ bd3,    // [32]
    float* __restrict__ out,          // [n,32]
    int n)
{
    __shared__ ull sA[32 * 32];   // Wd1 rows 0..31 as pairs: sA[k*32 + jp]
    __shared__ ull sW2[64 * 16];  // Wd2 pairs: sW2[k*16 + jp]
    __shared__ ull sW3[32 * 16];  // Wd3 pairs
    __shared__ ull sC1[32];       // c1 pairs
    __shared__ ull sB2[16];       // bd2 pairs
    __shared__ ull sB3[16];       // bd3 pairs

    const int tid = threadIdx.x;
    {
        const ull* gA  = (const ull*)Wd1;  // first 2048 floats = rows 0..31
        const ull* gW2 = (const ull*)Wd2;
        const ull* gW3 = (const ull*)Wd3;
        for (int i = tid; i < 1024; i += 64) { sA[i] = gA[i]; sW2[i] = gW2[i]; }
        for (int i = tid; i < 512;  i += 64) sW3[i] = gW3[i];
        if (tid < 32) sC1[tid] = ((const ull*)g_c1)[tid];
        if (tid < 16) { sB2[tid] = ((const ull*)bd2)[tid]; sB3[tid] = ((const ull*)bd3)[tid]; }
    }
    __syncthreads();

    const int r0 = blockIdx.x * 128 + tid;
    const int r1 = r0 + 64;
    const bool v0 = (r0 < n);
    const bool v1 = (r1 < n);

    // Load the two embedding rows (vectorized).
    float zeA[32], zeB[32];
#pragma unroll
    for (int q = 0; q < 8; q++) {
        float4 a = make_float4(0.f, 0.f, 0.f, 0.f);
        float4 b = a;
        if (v0) a = ((const float4*)(ze + (size_t)r0 * 32))[q];
        if (v1) b = ((const float4*)(ze + (size_t)r1 * 32))[q];
        zeA[4*q+0] = a.x; zeA[4*q+1] = a.y; zeA[4*q+2] = a.z; zeA[4*q+3] = a.w;
        zeB[4*q+0] = b.x; zeB[4*q+1] = b.y; zeB[4*q+2] = b.z; zeB[4*q+3] = b.w;
    }

    // h2 accumulators (layer-2 pre-activation), initialized with bd2.
    ull h2A[16], h2B[16];
#pragma unroll
    for (int jp = 0; jp < 16; jp++) { h2A[jp] = sB2[jp]; h2B[jp] = h2A[jp]; }

    // Layer 1 in two column-halves of 32 (keeps register pressure bounded);
    // each half is relu'd and immediately folded into the h2 accumulators.
#pragma unroll
    for (int half = 0; half < 2; half++) {
        ull aA[16], aB[16];
#pragma unroll
        for (int jp = 0; jp < 16; jp++) { aA[jp] = sC1[half * 16 + jp]; aB[jp] = aA[jp]; }

#pragma unroll
        for (int k = 0; k < 32; k++) {
            const ull z0 = pack2(zeA[k], zeA[k]);
            const ull z1 = pack2(zeB[k], zeB[k]);
#pragma unroll
            for (int jp = 0; jp < 16; jp++) {
                const ull w = sA[k * 32 + half * 16 + jp];
                aA[jp] = fma2(z0, w, aA[jp]);
                aB[jp] = fma2(z1, w, aB[jp]);
            }
        }

        // relu(h1 half) @ Wd2[half*32 : half*32+32, :]  ->  h2 accumulators
#pragma unroll
        for (int kp = 0; kp < 16; kp++) {
            const float2 pA = unpack2(aA[kp]);
            const float2 pB = unpack2(aB[kp]);
            const float hA0 = fmaxf(pA.x, 0.f), hA1 = fmaxf(pA.y, 0.f);
            const float hB0 = fmaxf(pB.x, 0.f), hB1 = fmaxf(pB.y, 0.f);
            const int kg = half * 32 + 2 * kp;
            const ull zA0 = pack2(hA0, hA0), zA1 = pack2(hA1, hA1);
            const ull zB0 = pack2(hB0, hB0), zB1 = pack2(hB1, hB1);
#pragma unroll
            for (int jp = 0; jp < 16; jp++) {
                const ull w0 = sW2[kg * 16 + jp];
                const ull w1 = sW2[(kg + 1) * 16 + jp];
                h2A[jp] = fma2(zA0, w0, h2A[jp]);
                h2A[jp] = fma2(zA1, w1, h2A[jp]);
                h2B[jp] = fma2(zB0, w0, h2B[jp]);
                h2B[jp] = fma2(zB1, w1, h2B[jp]);
            }
        }
    }

    // Layer 3: out = relu(h2) @ Wd3 + bd3
    ull oA[16], oB[16];
#pragma unroll
    for (int jp = 0; jp < 16; jp++) { oA[jp] = sB3[jp]; oB[jp] = oA[jp]; }
#pragma unroll
    for (int kp = 0; kp < 16; kp++) {
        const float2 pA = unpack2(h2A[kp]);
        const float2 pB = unpack2(h2B[kp]);
        const float hA0 = fmaxf(pA.x, 0.f), hA1 = fmaxf(pA.y, 0.f);
        const float hB0 = fmaxf(pB.x, 0.f), hB1 = fmaxf(pB.y, 0.f);
        const ull zA0 = pack2(hA0, hA0), zA1 = pack2(hA1, hA1);
        const ull zB0 = pack2(hB0, hB0), zB1 = pack2(hB1, hB1);
#pragma unroll
        for (int jp = 0; jp < 16; jp++) {
            const ull w0 = sW3[(2 * kp) * 16 + jp];
            const ull w1 = sW3[(2 * kp + 1) * 16 + jp];
            oA[jp] = fma2(zA0, w0, oA[jp]);
            oA[jp] = fma2(zA1, w1, oA[jp]);
            oB[jp] = fma2(zB0, w0, oB[jp]);
            oB[jp] = fma2(zB1, w1, oB[jp]);
        }
    }

    // Store (each ull already holds two consecutive output floats).
    if (v0) {
        ulonglong2* p = (ulonglong2*)(out + (size_t)r0 * 32);
#pragma unroll
        for (int q = 0; q < 8; q++) p[q] = make_ulonglong2(oA[2 * q], oA[2 * q + 1]);
    }
    if (v1) {
        ulonglong2* p = (ulonglong2*)(out + (size_t)r1 * 32);
#pragma unroll
        for (int q = 0; q < 8; q++) p[q] = make_ulonglong2(oB[2 * q], oB[2 * q + 1]);
    }
}

// ---------------------------------------------------------------------------
// Launch. Input order (metadata): 0 t, 1 zone_embedding, 2 zone_features,
// 3 person_attrs, 4 edge_index, 5 W1, 6 b1, 7 W2, 8 b2, 9 Wt1, 10 bt1,
// 11 Wt2, 12 bt2, 13 Wd1, 14 bd1, 15 Wd2, 16 bd2, 17 Wd3, 18 bd3.
// Output: [n_zones, 32] float32.
// ---------------------------------------------------------------------------
extern "C" void kernel_launch(void* const* d_in, const int* in_sizes, int n_in,
                              void* d_out, int out_size)
{
    const float* t      = (const float*)d_in[0];
    const float* ze     = (const float*)d_in[1];
    const float* person = (const float*)d_in[3];
    const float* Wt1    = (const float*)d_in[9];
    const float* bt1    = (const float*)d_in[10];
    const float* Wt2    = (const float*)d_in[11];
    const float* bt2    = (const float*)d_in[12];
    const float* Wd1    = (const float*)d_in[13];
    const float* bd1    = (const float*)d_in[14];
    const float* Wd2    = (const float*)d_in[15];
    const float* bd2    = (const float*)d_in[16];
    const float* Wd3    = (const float*)d_in[17];
    const float* bd3    = (const float*)d_in[18];
    float* out = (float*)d_out;

    const int n = in_sizes[1] / 32;

    prep_kernel<<<1, 64>>>(t, person, Wt1, bt1, Wt2, bt2, Wd1, bd1);

    const int blocks = (n + 127) / 128;
    zone_mlp_kernel<<<blocks, 64>>>(ze, Wd1, Wd2, bd2, Wd3, bd3, out, n);
}